// round 15
// baseline (speedup 1.0000x reference)
#include <cuda_runtime.h>
#include <cuda_bf16.h>
#include <math.h>
#include <stdint.h>

#define BATCH 2
#define TSEQ  2048
#define EDIM  1024
#define NHEAD 16
#define DHEAD 64
#define MTOT  (BATCH*TSEQ)   // 4096

// ---------------------------------------------------------------------------
// Scratch (static device globals: allocation-free, graph-safe)
// ---------------------------------------------------------------------------
static __device__ __nv_bfloat16  g_xhi[(size_t)MTOT * EDIM];
static __device__ __nv_bfloat16  g_xlo[(size_t)MTOT * EDIM];
static __device__ __nv_bfloat16  g_wthi[(size_t)3 * EDIM * EDIM];   // [z][n=h*64+d][e]
static __device__ __nv_bfloat16  g_wtlo[(size_t)3 * EDIM * EDIM];
static __device__ __nv_bfloat16  g_wohi[(size_t)EDIM * EDIM];       // [n][k]
static __device__ __nv_bfloat16  g_wolo[(size_t)EDIM * EDIM];
static __device__ __nv_bfloat16  g_athi[(size_t)MTOT * EDIM];       // [m][h*64+d]
static __device__ __nv_bfloat16  g_atlo[(size_t)MTOT * EDIM];
// QKV in bf16 hi/lo: [z][h][m=b*T+t][d]
static __device__ __nv_bfloat16  g_pqkvh[(size_t)3 * NHEAD * MTOT * DHEAD];
static __device__ __nv_bfloat16  g_pqkvl[(size_t)3 * NHEAD * MTOT * DHEAD];

// ---------------------------------------------------------------------------
// Portable (sm_100 base) tensor-core helpers
// ---------------------------------------------------------------------------
__device__ __forceinline__ uint32_t smem_u32(const void* p) {
    uint32_t a;
    asm("{ .reg .u64 t; cvta.to.shared.u64 t, %1; cvt.u32.u64 %0, t; }" : "=r"(a) : "l"(p));
    return a;
}
#define CP_ASYNC16(saddr, gptr) \
    asm volatile("cp.async.cg.shared.global [%0], [%1], 16;" :: "r"(saddr), "l"(gptr))
#define CP_COMMIT() asm volatile("cp.async.commit_group;" ::: "memory")
#define CP_WAIT0()  asm volatile("cp.async.wait_group 0;" ::: "memory")

#define LDSM_X4(r0, r1, r2, r3, addr) \
    asm volatile("ldmatrix.sync.aligned.m8n8.x4.shared.b16 {%0,%1,%2,%3}, [%4];" \
                 : "=r"(r0), "=r"(r1), "=r"(r2), "=r"(r3) : "r"(addr))
#define LDSM_X4_T(r0, r1, r2, r3, addr) \
    asm volatile("ldmatrix.sync.aligned.m8n8.x4.trans.shared.b16 {%0,%1,%2,%3}, [%4];" \
                 : "=r"(r0), "=r"(r1), "=r"(r2), "=r"(r3) : "r"(addr))

#define MMA16816(d, a, b0, b1) \
    asm volatile("mma.sync.aligned.m16n8k16.row.col.f32.bf16.bf16.f32 " \
                 "{%0,%1,%2,%3}, {%4,%5,%6,%7}, {%8,%9}, {%0,%1,%2,%3};" \
                 : "+f"((d)[0]), "+f"((d)[1]), "+f"((d)[2]), "+f"((d)[3]) \
                 : "r"((a)[0]), "r"((a)[1]), "r"((a)[2]), "r"((a)[3]), "r"(b0), "r"(b1))

__device__ __forceinline__ uint32_t swz(uint32_t off) {
    return off ^ ((off >> 3) & 0x70);
}
__device__ __forceinline__ float ex2f(float x) {
    float y; asm("ex2.approx.f32 %0, %1;" : "=f"(y) : "f"(x)); return y;
}
__device__ __forceinline__ void split2(float v0, float v1, uint32_t& hi, uint32_t& lo) {
    __nv_bfloat16 h0 = __float2bfloat16(v0), h1 = __float2bfloat16(v1);
    __nv_bfloat162 hp(h0, h1);
    hi = *(const uint32_t*)&hp;
    __nv_bfloat162 lp(__float2bfloat16(v0 - __bfloat162float(h0)),
                      __float2bfloat16(v1 - __bfloat162float(h1)));
    lo = *(const uint32_t*)&lp;
}

// ---------------------------------------------------------------------------
// Conversion kernels: fp32 -> bf16 hi/lo
// ---------------------------------------------------------------------------
__global__ void conv_elem(const float* __restrict__ src, int mode)
{
    __nv_bfloat16* hi = (mode == 0) ? g_xhi : g_wohi;
    __nv_bfloat16* lo = (mode == 0) ? g_xlo : g_wolo;
    const int i4 = blockIdx.x * blockDim.x + threadIdx.x;
    float4 v = *(const float4*)(src + (size_t)i4 * 4);
    uint32_t h0, l0, h1, l1;
    split2(v.x, v.y, h0, l0);
    split2(v.z, v.w, h1, l1);
    *(uint32_t*)(hi + (size_t)i4 * 4)     = h0;
    *(uint32_t*)(hi + (size_t)i4 * 4 + 2) = h1;
    *(uint32_t*)(lo + (size_t)i4 * 4)     = l0;
    *(uint32_t*)(lo + (size_t)i4 * 4 + 2) = l1;
}

// W[z][h][e][d] -> Wt[z][n=h*64+d][e], coalesced both sides via smem tile.
__global__ __launch_bounds__(256) void conv_w_t(
    const float* __restrict__ Wq, const float* __restrict__ Wk,
    const float* __restrict__ Wv)
{
    __shared__ float tile[32][65];
    const int z = blockIdx.z, h = blockIdx.y, e0 = blockIdx.x * 32;
    const float* W = ((z == 0) ? Wq : (z == 1) ? Wk : Wv) + (size_t)h * EDIM * DHEAD;
    const int tid = threadIdx.x;
    {
        const int e = tid >> 3, d0 = (tid & 7) * 8;
#pragma unroll
        for (int i = 0; i < 8; i++)
            tile[e][d0 + i] = W[(size_t)(e0 + e) * DHEAD + d0 + i];
    }
    __syncthreads();
    {
        const int d = tid >> 2, eo = (tid & 3) * 8;
        const size_t base = (size_t)z * EDIM * EDIM
                          + (size_t)(h * DHEAD + d) * EDIM + e0 + eo;
#pragma unroll
        for (int i = 0; i < 8; i++) {
            float v = tile[eo + i][d];
            __nv_bfloat16 hh = __float2bfloat16(v);
            g_wthi[base + i] = hh;
            g_wtlo[base + i] = __float2bfloat16(v - __bfloat162float(hh));
        }
    }
}

// ---------------------------------------------------------------------------
// bf16x3 mma.sync GEMM, 2 CTAs/SM: CTA 128x64, BK=64, 2-stage cp.async,
// 96KB smem, 8 warps (4M x 2N), warp tile 32x32, register-level fragment
// double buffering + boundary barrier hoisted before the last mmab.
// (unchanged from round 13)
// ---------------------------------------------------------------------------
#define MMSTAGE 49152   // Ah 16K | Al 16K | Bh 8K | Bl 8K

__global__ __launch_bounds__(256, 2) void mm64(float* __restrict__ Cout, int mode)
{
    extern __shared__ char smem[];
    const uint32_t sb = smem_u32(smem);
    const int tid = threadIdx.x;
    const int wid = tid >> 5, lane = tid & 31;
    const int z = blockIdx.z;
    const int m0 = blockIdx.y * 128;
    const int n0 = blockIdx.x * 64;

    const __nv_bfloat16* Ah = (mode == 0) ? g_xhi : g_athi;
    const __nv_bfloat16* Al = (mode == 0) ? g_xlo : g_atlo;
    const __nv_bfloat16* Bh = (mode == 0) ? (g_wthi + (size_t)z * EDIM * EDIM) : g_wohi;
    const __nv_bfloat16* Bl = (mode == 0) ? (g_wtlo + (size_t)z * EDIM * EDIM) : g_wolo;

    const int ra  = tid >> 1;
    const int cba = (tid & 1) * 32;
    const int rb  = tid >> 2;
    const int cbb = (tid & 3) * 16;
    const size_t ga_row = (size_t)(m0 + ra) * EDIM;
    const size_t gb_row = (size_t)(n0 + rb) * EDIM;

    auto load_stage = [&](int s, int k0) {
        const uint32_t base = sb + (uint32_t)s * MMSTAGE;
#pragma unroll
        for (int q = 0; q < 4; q++) {
            const int c = cba + q * 8;
            const uint32_t sw = swz((uint32_t)ra * 128u + (uint32_t)c * 2u);
            CP_ASYNC16(base + sw,          Ah + ga_row + k0 + c);
            CP_ASYNC16(base + 16384 + sw,  Al + ga_row + k0 + c);
        }
#pragma unroll
        for (int q = 0; q < 2; q++) {
            const int c = cbb + q * 8;
            const uint32_t sw = swz((uint32_t)rb * 128u + (uint32_t)c * 2u);
            CP_ASYNC16(base + 32768 + sw,  Bh + gb_row + k0 + c);
            CP_ASYNC16(base + 40960 + sw,  Bl + gb_row + k0 + c);
        }
        CP_COMMIT();
    };

    const int wm = wid >> 1;
    const int wn = wid & 1;
    const int lrow = lane & 15;
    const int lkh  = lane >> 4;

    uint32_t ah[2][2][4], al[2][2][4], bh[2][2][4], bl[2][2][4];
    float d[2][4][4];
#pragma unroll
    for (int i = 0; i < 2; i++)
#pragma unroll
        for (int j = 0; j < 4; j++)
#pragma unroll
            for (int c = 0; c < 4; c++) d[i][j][c] = 0.f;

    auto ldfr = [&](int fb, uint32_t st, int ks) {
        const uint32_t kcol = (uint32_t)(ks * 16 + lkh * 8) * 2u;
#pragma unroll
        for (int i = 0; i < 2; i++) {
            const uint32_t off = swz((uint32_t)(wm * 32 + i * 16 + lrow) * 128u + kcol);
            LDSM_X4(ah[fb][i][0], ah[fb][i][1], ah[fb][i][2], ah[fb][i][3], st + off);
            LDSM_X4(al[fb][i][0], al[fb][i][1], al[fb][i][2], al[fb][i][3], st + 16384 + off);
        }
#pragma unroll
        for (int j = 0; j < 2; j++) {
            const uint32_t off = swz((uint32_t)(wn * 32 + j * 16 + lrow) * 128u + kcol);
            LDSM_X4(bh[fb][j][0], bh[fb][j][1], bh[fb][j][2], bh[fb][j][3], st + 32768 + off);
            LDSM_X4(bl[fb][j][0], bl[fb][j][1], bl[fb][j][2], bl[fb][j][3], st + 40960 + off);
        }
    };

    auto mmab = [&](int fb) {
#pragma unroll
        for (int i = 0; i < 2; i++)
#pragma unroll
            for (int j = 0; j < 2; j++) {
                MMA16816(d[i][2*j],   ah[fb][i], bh[fb][j][0], bh[fb][j][2]);
                MMA16816(d[i][2*j+1], ah[fb][i], bh[fb][j][1], bh[fb][j][3]);
            }
#pragma unroll
        for (int i = 0; i < 2; i++)
#pragma unroll
            for (int j = 0; j < 2; j++) {
                MMA16816(d[i][2*j],   ah[fb][i], bl[fb][j][0], bl[fb][j][2]);
                MMA16816(d[i][2*j+1], ah[fb][i], bl[fb][j][1], bl[fb][j][3]);
            }
#pragma unroll
        for (int i = 0; i < 2; i++)
#pragma unroll
            for (int j = 0; j < 2; j++) {
                MMA16816(d[i][2*j],   al[fb][i], bh[fb][j][0], bh[fb][j][2]);
                MMA16816(d[i][2*j+1], al[fb][i], bh[fb][j][1], bh[fb][j][3]);
            }
    };

    load_stage(0, 0);
    CP_WAIT0();
    __syncthreads();
    ldfr(0, sb, 0);
    load_stage(1, 64);

#pragma unroll 1
    for (int kb = 0; kb < 16; kb++) {
        const int cur = kb & 1;
        const uint32_t st = sb + (uint32_t)cur * MMSTAGE;
        ldfr(1, st, 1); mmab(0);
        ldfr(0, st, 2); mmab(1);
        ldfr(1, st, 3); mmab(0);
        if (kb < 15) {
            CP_WAIT0();
            __syncthreads();
            ldfr(0, sb + (uint32_t)(cur ^ 1) * MMSTAGE, 0);
            mmab(1);
            if (kb < 14) load_stage(cur, (kb + 2) * 64);
        } else {
            mmab(1);
        }
    }

    const int qrow = lane >> 2, qcol = (lane & 3) * 2;
#pragma unroll
    for (int i = 0; i < 2; i++) {
#pragma unroll
        for (int j = 0; j < 4; j++) {
            const int n = n0 + wn * 32 + j * 8 + qcol;
            const int m1 = m0 + wm * 32 + i * 16 + qrow;
#pragma unroll
            for (int hh = 0; hh < 2; hh++) {
                const int m = m1 + hh * 8;
                const float v0 = d[i][j][hh * 2 + 0];
                const float v1 = d[i][j][hh * 2 + 1];
                if (mode == 0) {
                    const size_t base = (size_t)(n >> 6) * (MTOT * DHEAD)
                                      + (size_t)m * DHEAD + (n & 63);
                    uint32_t hi, lo;
                    split2(v0, v1, hi, lo);
                    *(uint32_t*)(g_pqkvh + (size_t)z * NHEAD * MTOT * DHEAD + base) = hi;
                    *(uint32_t*)(g_pqkvl + (size_t)z * NHEAD * MTOT * DHEAD + base) = lo;
                } else {
                    float* dst = Cout + (size_t)m * EDIM + n;
                    dst[0] = v0; dst[1] = v1;
                }
            }
        }
    }
}

// ---------------------------------------------------------------------------
// Flash attention, 2 CTAs/SM: 128 q-rows/CTA, KV tiles of 64,
// double-buffered cp.async + register-level fragment double buffering.
// Round-13 structure, plus ONE change: the PV loop's first V-fragment load
// is hoisted before the softmax (latency hidden under mask/softmax work).
// ---------------------------------------------------------------------------
#define FA_SMEM (32768 + 2 * 32768)   // Q hi/lo 32K + 2 KV stages of 32K

__global__ __launch_bounds__(256, 2) void flash_mma()
{
    extern __shared__ char fsm[];
    const uint32_t sb = smem_u32(fsm);
    const int tid = threadIdx.x;
    const int wid = tid >> 5, lane = tid & 31;
    const int h = blockIdx.y >> 1;
    const int b = blockIdx.y & 1;
    const int i0 = (int)(gridDim.x - 1 - blockIdx.x) * 128;  // heavy tiles first
    const int ntiles = i0 / 64 + 2;

    const size_t hb = ((size_t)h * MTOT + (size_t)b * TSEQ) * DHEAD;
    const __nv_bfloat16* Qh = g_pqkvh + hb;
    const __nv_bfloat16* Ql = g_pqkvl + hb;
    const __nv_bfloat16* Kh = g_pqkvh + (size_t)NHEAD * MTOT * DHEAD + hb;
    const __nv_bfloat16* Kl = g_pqkvl + (size_t)NHEAD * MTOT * DHEAD + hb;
    const __nv_bfloat16* Vh = g_pqkvh + (size_t)2 * NHEAD * MTOT * DHEAD + hb;
    const __nv_bfloat16* Vl = g_pqkvl + (size_t)2 * NHEAD * MTOT * DHEAD + hb;

    const int rq  = tid >> 1;
    const int cbq = (tid & 1) * 32;
    const int rk  = tid >> 2;
    const int cbk = (tid & 3) * 16;

    // Q (one-time) + KV stage 0, one commit group
#pragma unroll
    for (int q = 0; q < 4; q++) {
        const int c = cbq + q * 8;
        const uint32_t sw = swz((uint32_t)rq * 128u + (uint32_t)c * 2u);
        CP_ASYNC16(sb + sw,          Qh + (size_t)(i0 + rq) * DHEAD + c);
        CP_ASYNC16(sb + 16384 + sw,  Ql + (size_t)(i0 + rq) * DHEAD + c);
    }
    auto load_kv = [&](int s, int t) {
        const uint32_t base = sb + 32768 + (uint32_t)s * 32768;
        const size_t g = (size_t)(t * 64 + rk) * DHEAD;
#pragma unroll
        for (int q = 0; q < 2; q++) {
            const int c = cbk + q * 8;
            const uint32_t sw = swz((uint32_t)rk * 128u + (uint32_t)c * 2u);
            CP_ASYNC16(base + sw,          Kh + g + c);
            CP_ASYNC16(base + 8192 + sw,   Kl + g + c);
            CP_ASYNC16(base + 16384 + sw,  Vh + g + c);
            CP_ASYNC16(base + 24576 + sw,  Vl + g + c);
        }
        CP_COMMIT();
    };
    load_kv(0, 0);

    const float SC = 1.4426950408889634f * 0.02209708691207961f;  // log2(e)/sqrt(T)

    uint32_t qh[4][4], ql[4][4];
    float o[8][4];
#pragma unroll
    for (int j = 0; j < 8; j++)
#pragma unroll
        for (int c = 0; c < 4; c++) o[j][c] = 0.f;
    float m0r = -INFINITY, m1r = -INFINITY, l0 = 0.f, l1 = 0.f;

    const int rt0 = wid * 16 + (lane >> 2);
    const int lrow = lane & 15;
    const int lkh  = lane >> 4;

#pragma unroll 1
    for (int t = 0; t < ntiles; t++) {
        const int cur = t & 1;
        CP_WAIT0();
        __syncthreads();
        if (t == 0) {
#pragma unroll
            for (int kk = 0; kk < 4; kk++) {
                const uint32_t off = swz((uint32_t)(wid * 16 + lrow) * 128u
                                         + (uint32_t)(kk * 16 + lkh * 8) * 2u);
                LDSM_X4(qh[kk][0], qh[kk][1], qh[kk][2], qh[kk][3], sb + off);
                LDSM_X4(ql[kk][0], ql[kk][1], ql[kk][2], ql[kk][3], sb + 16384 + off);
            }
        }
        if (t + 1 < ntiles) load_kv(cur ^ 1, t + 1);

        const uint32_t st = sb + 32768 + (uint32_t)cur * 32768;

        // V fragments + loader declared up front so ldV(0,0) can be hoisted
        uint32_t vfh[2][4], vfl[2][4];
        auto ldV = [&](int fb, int idx) {
            const int kk = idx >> 2, jj = idx & 3;
            const uint32_t off = swz((uint32_t)(kk * 16 + lrow) * 128u
                                     + (uint32_t)(jj * 16 + lkh * 8) * 2u);
            LDSM_X4_T(vfh[fb][0], vfh[fb][1], vfh[fb][2], vfh[fb][3], st + 16384 + off);
            LDSM_X4_T(vfl[fb][0], vfl[fb][1], vfl[fb][2], vfl[fb][3], st + 24576 + off);
        };

        // ---- S = Q K^T (64 cols per warp), K-frag double buffered ----
        float s[8][4];
#pragma unroll
        for (int j = 0; j < 8; j++)
#pragma unroll
            for (int c = 0; c < 4; c++) s[j][c] = 0.f;

        {
            uint32_t kfh[2][4], kfl[2][4];
            auto ldK = [&](int fb, int idx) {
                const int kk = idx >> 2, jj = idx & 3;
                const uint32_t off = swz((uint32_t)(jj * 16 + lrow) * 128u
                                         + (uint32_t)(kk * 16 + lkh * 8) * 2u);
                LDSM_X4(kfh[fb][0], kfh[fb][1], kfh[fb][2], kfh[fb][3], st + off);
                LDSM_X4(kfl[fb][0], kfl[fb][1], kfl[fb][2], kfl[fb][3], st + 8192 + off);
            };
            ldK(0, 0);
#pragma unroll
            for (int idx = 0; idx < 16; idx++) {
                const int fb = idx & 1;
                if (idx < 15) ldK(fb ^ 1, idx + 1);
                const int kk = idx >> 2, jj = idx & 3;
                MMA16816(s[2*jj],   qh[kk], kfh[fb][0], kfh[fb][2]);
                MMA16816(s[2*jj+1], qh[kk], kfh[fb][1], kfh[fb][3]);
                MMA16816(s[2*jj],   qh[kk], kfl[fb][0], kfl[fb][2]);
                MMA16816(s[2*jj+1], qh[kk], kfl[fb][1], kfl[fb][3]);
                MMA16816(s[2*jj],   ql[kk], kfh[fb][0], kfh[fb][2]);
                MMA16816(s[2*jj+1], ql[kk], kfh[fb][1], kfh[fb][3]);
            }
        }

        // hoisted PV idx0 V-fragment load (latency hidden under softmax)
        ldV(0, 0);

        // ---- causal mask (only the last two 64-wide tiles can cross the diag) ----
        if (t >= ntiles - 2) {
            const int row0 = i0 + rt0;
#pragma unroll
            for (int j = 0; j < 8; j++) {
#pragma unroll
                for (int c = 0; c < 2; c++) {
                    const int ct = t * 64 + j * 8 + (lane & 3) * 2 + c;
                    if (ct > row0)     s[j][c]     = -INFINITY;
                    if (ct > row0 + 8) s[j][c + 2] = -INFINITY;
                }
            }
        }

        // ---- online softmax ----
        float mx0 = -INFINITY, mx1 = -INFINITY;
#pragma unroll
        for (int j = 0; j < 8; j++) {
            mx0 = fmaxf(mx0, fmaxf(s[j][0], s[j][1]));
            mx1 = fmaxf(mx1, fmaxf(s[j][2], s[j][3]));
        }
        mx0 = fmaxf(mx0, __shfl_xor_sync(0xffffffffu, mx0, 1));
        mx0 = fmaxf(mx0, __shfl_xor_sync(0xffffffffu, mx0, 2));
        mx1 = fmaxf(mx1, __shfl_xor_sync(0xffffffffu, mx1, 1));
        mx1 = fmaxf(mx1, __shfl_xor_sync(0xffffffffu, mx1, 2));
        const float mn0 = fmaxf(m0r, mx0);
        const float mn1 = fmaxf(m1r, mx1);
        const float c0 = ex2f((m0r - mn0) * SC);
        const float c1 = ex2f((m1r - mn1) * SC);
        m0r = mn0; m1r = mn1;

        float ls0 = 0.f, ls1 = 0.f;
#pragma unroll
        for (int j = 0; j < 8; j++) {
            s[j][0] = ex2f((s[j][0] - mn0) * SC);
            s[j][1] = ex2f((s[j][1] - mn0) * SC);
            s[j][2] = ex2f((s[j][2] - mn1) * SC);
            s[j][3] = ex2f((s[j][3] - mn1) * SC);
            ls0 += s[j][0] + s[j][1];
            ls1 += s[j][2] + s[j][3];
        }
        ls0 += __shfl_xor_sync(0xffffffffu, ls0, 1);
        ls0 += __shfl_xor_sync(0xffffffffu, ls0, 2);
        ls1 += __shfl_xor_sync(0xffffffffu, ls1, 1);
        ls1 += __shfl_xor_sync(0xffffffffu, ls1, 2);
        l0 = l0 * c0 + ls0;
        l1 = l1 * c1 + ls1;
#pragma unroll
        for (int j = 0; j < 8; j++) {
            o[j][0] *= c0; o[j][1] *= c0; o[j][2] *= c1; o[j][3] *= c1;
        }

        // ---- O += P V, V-frag double buffered (idx0 already loaded) ----
        {
            uint32_t ahi[4], alo[4];
#pragma unroll
            for (int idx = 0; idx < 16; idx++) {
                const int fb = idx & 1;
                const int kk = idx >> 2, jj = idx & 3;
                if (jj == 0) {
                    split2(s[2*kk][0],   s[2*kk][1],   ahi[0], alo[0]);
                    split2(s[2*kk][2],   s[2*kk][3],   ahi[1], alo[1]);
                    split2(s[2*kk+1][0], s[2*kk+1][1], ahi[2], alo[2]);
                    split2(s[2*kk+1][2], s[2*kk+1][3], ahi[3], alo[3]);
                }
                if (idx < 15) ldV(fb ^ 1, idx + 1);
                MMA16816(o[2*jj],   ahi, vfh[fb][0], vfh[fb][1]);
                MMA16816(o[2*jj+1], ahi, vfh[fb][2], vfh[fb][3]);
                MMA16816(o[2*jj],   alo, vfh[fb][0], vfh[fb][1]);
                MMA16816(o[2*jj+1], alo, vfh[fb][2], vfh[fb][3]);
                MMA16816(o[2*jj],   ahi, vfl[fb][0], vfl[fb][1]);
                MMA16816(o[2*jj+1], ahi, vfl[fb][2], vfl[fb][3]);
            }
        }
    }

    // ---- epilogue: normalize, write att as bf16 hi/lo at [b*T+t][h*64+d] ----
    const float inv0 = 1.0f / l0;
    const float inv1 = 1.0f / l1;
    const int colb = h * DHEAD + (lane & 3) * 2;
    const size_t row0 = (size_t)(b * TSEQ + i0 + rt0);
#pragma unroll
    for (int j = 0; j < 8; j++) {
        uint32_t hi, lo;
        const size_t idx0 = row0 * EDIM + colb + j * 8;
        split2(o[j][0] * inv0, o[j][1] * inv0, hi, lo);
        *(uint32_t*)(g_athi + idx0) = hi;
        *(uint32_t*)(g_atlo + idx0) = lo;
        const size_t idx1 = idx0 + (size_t)8 * EDIM;
        split2(o[j][2] * inv1, o[j][3] * inv1, hi, lo);
        *(uint32_t*)(g_athi + idx1) = hi;
        *(uint32_t*)(g_atlo + idx1) = lo;
    }
}

// ---------------------------------------------------------------------------
extern "C" void kernel_launch(void* const* d_in, const int* in_sizes, int n_in,
                              void* d_out, int out_size)
{
    const float* x  = (const float*)d_in[0];
    const float* Wq = (const float*)d_in[2];
    const float* Wk = (const float*)d_in[3];
    const float* Wv = (const float*)d_in[4];
    const float* Wo = (const float*)d_in[5];
    float* out = (float*)d_out;

    cudaFuncSetAttribute(mm64, cudaFuncAttributeMaxDynamicSharedMemorySize, 2 * MMSTAGE);
    cudaFuncSetAttribute(flash_mma, cudaFuncAttributeMaxDynamicSharedMemorySize, FA_SMEM);

    // 1) fp32 -> bf16 hi/lo conversions
    conv_elem<<<(MTOT * EDIM) / (256 * 4), 256>>>(x, 0);
    conv_elem<<<(EDIM * EDIM) / (256 * 4), 256>>>(Wo, 1);
    {
        dim3 g(EDIM / 32, NHEAD, 3);
        conv_w_t<<<g, 256>>>(Wq, Wk, Wv);
    }

    // 2) QKV projection -> bf16 hi/lo [z][h][m][d]
    {
        dim3 g(EDIM / 64, MTOT / 128, 3);
        mm64<<<g, 256, 2 * MMSTAGE>>>(nullptr, 0);
    }

    // 3) Flash attention (bf16x3 tensor cores)
    {
        dim3 g(TSEQ / 128, NHEAD * BATCH);
        flash_mma<<<g, 256, FA_SMEM>>>();
    }

    // 4) Output projection
    {
        dim3 g(EDIM / 64, MTOT / 128, 1);
        mm64<<<g, 256, 2 * MMSTAGE>>>(out, 1);
    }
}

// round 16
// speedup vs baseline: 1.0298x; 1.0298x over previous
#include <cuda_runtime.h>
#include <cuda_bf16.h>
#include <math.h>
#include <stdint.h>

#define BATCH 2
#define TSEQ  2048
#define EDIM  1024
#define NHEAD 16
#define DHEAD 64
#define MTOT  (BATCH*TSEQ)   // 4096

// ---------------------------------------------------------------------------
// Scratch (static device globals: allocation-free, graph-safe)
// ---------------------------------------------------------------------------
static __device__ __nv_bfloat16  g_xhi[(size_t)MTOT * EDIM];
static __device__ __nv_bfloat16  g_xlo[(size_t)MTOT * EDIM];
static __device__ __nv_bfloat16  g_wthi[(size_t)3 * EDIM * EDIM];   // [z][n=h*64+d][e]
static __device__ __nv_bfloat16  g_wtlo[(size_t)3 * EDIM * EDIM];
static __device__ __nv_bfloat16  g_wohi[(size_t)EDIM * EDIM];       // [n][k]
static __device__ __nv_bfloat16  g_wolo[(size_t)EDIM * EDIM];
static __device__ __nv_bfloat16  g_athi[(size_t)MTOT * EDIM];       // [m][h*64+d]
static __device__ __nv_bfloat16  g_atlo[(size_t)MTOT * EDIM];
// QKV in bf16 hi/lo: [z][h][m=b*T+t][d]
static __device__ __nv_bfloat16  g_pqkvh[(size_t)3 * NHEAD * MTOT * DHEAD];
static __device__ __nv_bfloat16  g_pqkvl[(size_t)3 * NHEAD * MTOT * DHEAD];

// ---------------------------------------------------------------------------
// Portable (sm_100 base) tensor-core helpers
// ---------------------------------------------------------------------------
__device__ __forceinline__ uint32_t smem_u32(const void* p) {
    uint32_t a;
    asm("{ .reg .u64 t; cvta.to.shared.u64 t, %1; cvt.u32.u64 %0, t; }" : "=r"(a) : "l"(p));
    return a;
}
#define CP_ASYNC16(saddr, gptr) \
    asm volatile("cp.async.cg.shared.global [%0], [%1], 16;" :: "r"(saddr), "l"(gptr))
#define CP_COMMIT() asm volatile("cp.async.commit_group;" ::: "memory")
#define CP_WAIT0()  asm volatile("cp.async.wait_group 0;" ::: "memory")

#define LDSM_X4(r0, r1, r2, r3, addr) \
    asm volatile("ldmatrix.sync.aligned.m8n8.x4.shared.b16 {%0,%1,%2,%3}, [%4];" \
                 : "=r"(r0), "=r"(r1), "=r"(r2), "=r"(r3) : "r"(addr))
#define LDSM_X4_T(r0, r1, r2, r3, addr) \
    asm volatile("ldmatrix.sync.aligned.m8n8.x4.trans.shared.b16 {%0,%1,%2,%3}, [%4];" \
                 : "=r"(r0), "=r"(r1), "=r"(r2), "=r"(r3) : "r"(addr))

#define MMA16816(d, a, b0, b1) \
    asm volatile("mma.sync.aligned.m16n8k16.row.col.f32.bf16.bf16.f32 " \
                 "{%0,%1,%2,%3}, {%4,%5,%6,%7}, {%8,%9}, {%0,%1,%2,%3};" \
                 : "+f"((d)[0]), "+f"((d)[1]), "+f"((d)[2]), "+f"((d)[3]) \
                 : "r"((a)[0]), "r"((a)[1]), "r"((a)[2]), "r"((a)[3]), "r"(b0), "r"(b1))

__device__ __forceinline__ uint32_t swz(uint32_t off) {
    return off ^ ((off >> 3) & 0x70);
}
__device__ __forceinline__ float ex2f(float x) {
    float y; asm("ex2.approx.f32 %0, %1;" : "=f"(y) : "f"(x)); return y;
}
__device__ __forceinline__ void split2(float v0, float v1, uint32_t& hi, uint32_t& lo) {
    __nv_bfloat16 h0 = __float2bfloat16(v0), h1 = __float2bfloat16(v1);
    __nv_bfloat162 hp(h0, h1);
    hi = *(const uint32_t*)&hp;
    __nv_bfloat162 lp(__float2bfloat16(v0 - __bfloat162float(h0)),
                      __float2bfloat16(v1 - __bfloat162float(h1)));
    lo = *(const uint32_t*)&lp;
}

// ---------------------------------------------------------------------------
// Conversion kernels: fp32 -> bf16 hi/lo
// ---------------------------------------------------------------------------
__global__ void conv_elem(const float* __restrict__ src, int mode)
{
    __nv_bfloat16* hi = (mode == 0) ? g_xhi : g_wohi;
    __nv_bfloat16* lo = (mode == 0) ? g_xlo : g_wolo;
    const int i4 = blockIdx.x * blockDim.x + threadIdx.x;
    float4 v = *(const float4*)(src + (size_t)i4 * 4);
    uint32_t h0, l0, h1, l1;
    split2(v.x, v.y, h0, l0);
    split2(v.z, v.w, h1, l1);
    *(uint32_t*)(hi + (size_t)i4 * 4)     = h0;
    *(uint32_t*)(hi + (size_t)i4 * 4 + 2) = h1;
    *(uint32_t*)(lo + (size_t)i4 * 4)     = l0;
    *(uint32_t*)(lo + (size_t)i4 * 4 + 2) = l1;
}

// W[z][h][e][d] -> Wt[z][n=h*64+d][e], coalesced both sides via smem tile.
__global__ __launch_bounds__(256) void conv_w_t(
    const float* __restrict__ Wq, const float* __restrict__ Wk,
    const float* __restrict__ Wv)
{
    __shared__ float tile[32][65];
    const int z = blockIdx.z, h = blockIdx.y, e0 = blockIdx.x * 32;
    const float* W = ((z == 0) ? Wq : (z == 1) ? Wk : Wv) + (size_t)h * EDIM * DHEAD;
    const int tid = threadIdx.x;
    {
        const int e = tid >> 3, d0 = (tid & 7) * 8;
#pragma unroll
        for (int i = 0; i < 8; i++)
            tile[e][d0 + i] = W[(size_t)(e0 + e) * DHEAD + d0 + i];
    }
    __syncthreads();
    {
        const int d = tid >> 2, eo = (tid & 3) * 8;
        const size_t base = (size_t)z * EDIM * EDIM
                          + (size_t)(h * DHEAD + d) * EDIM + e0 + eo;
#pragma unroll
        for (int i = 0; i < 8; i++) {
            float v = tile[eo + i][d];
            __nv_bfloat16 hh = __float2bfloat16(v);
            g_wthi[base + i] = hh;
            g_wtlo[base + i] = __float2bfloat16(v - __bfloat162float(hh));
        }
    }
}

// ---------------------------------------------------------------------------
// bf16x3 mma.sync GEMM, 2 CTAs/SM: CTA 128x64, BK=64, 2-stage cp.async,
// 96KB smem, 8 warps (4M x 2N), warp tile 32x32, register-level fragment
// double buffering + boundary barrier hoisted before the last mmab.
// mode 0: A=x, B=Wt[z], C -> g_pqkvh/l.  mode 1: A=att, B=Wo, C -> out fp32.
// ---------------------------------------------------------------------------
#define MMSTAGE 49152   // Ah 16K | Al 16K | Bh 8K | Bl 8K

__global__ __launch_bounds__(256, 2) void mm64(float* __restrict__ Cout, int mode)
{
    extern __shared__ char smem[];
    const uint32_t sb = smem_u32(smem);
    const int tid = threadIdx.x;
    const int wid = tid >> 5, lane = tid & 31;
    const int z = blockIdx.z;
    const int m0 = blockIdx.y * 128;
    const int n0 = blockIdx.x * 64;

    const __nv_bfloat16* Ah = (mode == 0) ? g_xhi : g_athi;
    const __nv_bfloat16* Al = (mode == 0) ? g_xlo : g_atlo;
    const __nv_bfloat16* Bh = (mode == 0) ? (g_wthi + (size_t)z * EDIM * EDIM) : g_wohi;
    const __nv_bfloat16* Bl = (mode == 0) ? (g_wtlo + (size_t)z * EDIM * EDIM) : g_wolo;

    const int ra  = tid >> 1;
    const int cba = (tid & 1) * 32;
    const int rb  = tid >> 2;
    const int cbb = (tid & 3) * 16;
    const size_t ga_row = (size_t)(m0 + ra) * EDIM;
    const size_t gb_row = (size_t)(n0 + rb) * EDIM;

    auto load_stage = [&](int s, int k0) {
        const uint32_t base = sb + (uint32_t)s * MMSTAGE;
#pragma unroll
        for (int q = 0; q < 4; q++) {
            const int c = cba + q * 8;
            const uint32_t sw = swz((uint32_t)ra * 128u + (uint32_t)c * 2u);
            CP_ASYNC16(base + sw,          Ah + ga_row + k0 + c);
            CP_ASYNC16(base + 16384 + sw,  Al + ga_row + k0 + c);
        }
#pragma unroll
        for (int q = 0; q < 2; q++) {
            const int c = cbb + q * 8;
            const uint32_t sw = swz((uint32_t)rb * 128u + (uint32_t)c * 2u);
            CP_ASYNC16(base + 32768 + sw,  Bh + gb_row + k0 + c);
            CP_ASYNC16(base + 40960 + sw,  Bl + gb_row + k0 + c);
        }
        CP_COMMIT();
    };

    const int wm = wid >> 1;
    const int wn = wid & 1;
    const int lrow = lane & 15;
    const int lkh  = lane >> 4;

    uint32_t ah[2][2][4], al[2][2][4], bh[2][2][4], bl[2][2][4];
    float d[2][4][4];
#pragma unroll
    for (int i = 0; i < 2; i++)
#pragma unroll
        for (int j = 0; j < 4; j++)
#pragma unroll
            for (int c = 0; c < 4; c++) d[i][j][c] = 0.f;

    auto ldfr = [&](int fb, uint32_t st, int ks) {
        const uint32_t kcol = (uint32_t)(ks * 16 + lkh * 8) * 2u;
#pragma unroll
        for (int i = 0; i < 2; i++) {
            const uint32_t off = swz((uint32_t)(wm * 32 + i * 16 + lrow) * 128u + kcol);
            LDSM_X4(ah[fb][i][0], ah[fb][i][1], ah[fb][i][2], ah[fb][i][3], st + off);
            LDSM_X4(al[fb][i][0], al[fb][i][1], al[fb][i][2], al[fb][i][3], st + 16384 + off);
        }
#pragma unroll
        for (int j = 0; j < 2; j++) {
            const uint32_t off = swz((uint32_t)(wn * 32 + j * 16 + lrow) * 128u + kcol);
            LDSM_X4(bh[fb][j][0], bh[fb][j][1], bh[fb][j][2], bh[fb][j][3], st + 32768 + off);
            LDSM_X4(bl[fb][j][0], bl[fb][j][1], bl[fb][j][2], bl[fb][j][3], st + 40960 + off);
        }
    };

    auto mmab = [&](int fb) {
#pragma unroll
        for (int i = 0; i < 2; i++)
#pragma unroll
            for (int j = 0; j < 2; j++) {
                MMA16816(d[i][2*j],   ah[fb][i], bh[fb][j][0], bh[fb][j][2]);
                MMA16816(d[i][2*j+1], ah[fb][i], bh[fb][j][1], bh[fb][j][3]);
            }
#pragma unroll
        for (int i = 0; i < 2; i++)
#pragma unroll
            for (int j = 0; j < 2; j++) {
                MMA16816(d[i][2*j],   ah[fb][i], bl[fb][j][0], bl[fb][j][2]);
                MMA16816(d[i][2*j+1], ah[fb][i], bl[fb][j][1], bl[fb][j][3]);
            }
#pragma unroll
        for (int i = 0; i < 2; i++)
#pragma unroll
            for (int j = 0; j < 2; j++) {
                MMA16816(d[i][2*j],   al[fb][i], bh[fb][j][0], bh[fb][j][2]);
                MMA16816(d[i][2*j+1], al[fb][i], bh[fb][j][1], bh[fb][j][3]);
            }
    };

    load_stage(0, 0);
    CP_WAIT0();
    __syncthreads();
    ldfr(0, sb, 0);
    load_stage(1, 64);

#pragma unroll 1
    for (int kb = 0; kb < 16; kb++) {
        const int cur = kb & 1;
        const uint32_t st = sb + (uint32_t)cur * MMSTAGE;
        ldfr(1, st, 1); mmab(0);
        ldfr(0, st, 2); mmab(1);
        ldfr(1, st, 3); mmab(0);
        if (kb < 15) {
            CP_WAIT0();
            __syncthreads();
            ldfr(0, sb + (uint32_t)(cur ^ 1) * MMSTAGE, 0);
            mmab(1);
            if (kb < 14) load_stage(cur, (kb + 2) * 64);
        } else {
            mmab(1);
        }
    }

    const int qrow = lane >> 2, qcol = (lane & 3) * 2;
#pragma unroll
    for (int i = 0; i < 2; i++) {
#pragma unroll
        for (int j = 0; j < 4; j++) {
            const int n = n0 + wn * 32 + j * 8 + qcol;
            const int m1 = m0 + wm * 32 + i * 16 + qrow;
#pragma unroll
            for (int hh = 0; hh < 2; hh++) {
                const int m = m1 + hh * 8;
                const float v0 = d[i][j][hh * 2 + 0];
                const float v1 = d[i][j][hh * 2 + 1];
                if (mode == 0) {
                    const size_t base = (size_t)(n >> 6) * (MTOT * DHEAD)
                                      + (size_t)m * DHEAD + (n & 63);
                    uint32_t hi, lo;
                    split2(v0, v1, hi, lo);
                    *(uint32_t*)(g_pqkvh + (size_t)z * NHEAD * MTOT * DHEAD + base) = hi;
                    *(uint32_t*)(g_pqkvl + (size_t)z * NHEAD * MTOT * DHEAD + base) = lo;
                } else {
                    float* dst = Cout + (size_t)m * EDIM + n;
                    dst[0] = v0; dst[1] = v1;
                }
            }
        }
    }
}

// ---------------------------------------------------------------------------
// Flash attention, 2 CTAs/SM: 128 q-rows/CTA, KV tiles of 64,
// double-buffered cp.async + register-level fragment double buffering in
// both the S (QK^T) and PV loops.  (round-13 structure, proven best)
// ---------------------------------------------------------------------------
#define FA_SMEM (32768 + 2 * 32768)   // Q hi/lo 32K + 2 KV stages of 32K

__global__ __launch_bounds__(256, 2) void flash_mma()
{
    extern __shared__ char fsm[];
    const uint32_t sb = smem_u32(fsm);
    const int tid = threadIdx.x;
    const int wid = tid >> 5, lane = tid & 31;
    const int h = blockIdx.y >> 1;
    const int b = blockIdx.y & 1;
    const int i0 = (int)(gridDim.x - 1 - blockIdx.x) * 128;  // heavy tiles first
    const int ntiles = i0 / 64 + 2;

    const size_t hb = ((size_t)h * MTOT + (size_t)b * TSEQ) * DHEAD;
    const __nv_bfloat16* Qh = g_pqkvh + hb;
    const __nv_bfloat16* Ql = g_pqkvl + hb;
    const __nv_bfloat16* Kh = g_pqkvh + (size_t)NHEAD * MTOT * DHEAD + hb;
    const __nv_bfloat16* Kl = g_pqkvl + (size_t)NHEAD * MTOT * DHEAD + hb;
    const __nv_bfloat16* Vh = g_pqkvh + (size_t)2 * NHEAD * MTOT * DHEAD + hb;
    const __nv_bfloat16* Vl = g_pqkvl + (size_t)2 * NHEAD * MTOT * DHEAD + hb;

    const int rq  = tid >> 1;
    const int cbq = (tid & 1) * 32;
    const int rk  = tid >> 2;
    const int cbk = (tid & 3) * 16;

    // Q (one-time) + KV stage 0, one commit group
#pragma unroll
    for (int q = 0; q < 4; q++) {
        const int c = cbq + q * 8;
        const uint32_t sw = swz((uint32_t)rq * 128u + (uint32_t)c * 2u);
        CP_ASYNC16(sb + sw,          Qh + (size_t)(i0 + rq) * DHEAD + c);
        CP_ASYNC16(sb + 16384 + sw,  Ql + (size_t)(i0 + rq) * DHEAD + c);
    }
    auto load_kv = [&](int s, int t) {
        const uint32_t base = sb + 32768 + (uint32_t)s * 32768;
        const size_t g = (size_t)(t * 64 + rk) * DHEAD;
#pragma unroll
        for (int q = 0; q < 2; q++) {
            const int c = cbk + q * 8;
            const uint32_t sw = swz((uint32_t)rk * 128u + (uint32_t)c * 2u);
            CP_ASYNC16(base + sw,          Kh + g + c);
            CP_ASYNC16(base + 8192 + sw,   Kl + g + c);
            CP_ASYNC16(base + 16384 + sw,  Vh + g + c);
            CP_ASYNC16(base + 24576 + sw,  Vl + g + c);
        }
        CP_COMMIT();
    };
    load_kv(0, 0);

    const float SC = 1.4426950408889634f * 0.02209708691207961f;  // log2(e)/sqrt(T)

    uint32_t qh[4][4], ql[4][4];
    float o[8][4];
#pragma unroll
    for (int j = 0; j < 8; j++)
#pragma unroll
        for (int c = 0; c < 4; c++) o[j][c] = 0.f;
    float m0r = -INFINITY, m1r = -INFINITY, l0 = 0.f, l1 = 0.f;

    const int rt0 = wid * 16 + (lane >> 2);
    const int lrow = lane & 15;
    const int lkh  = lane >> 4;

#pragma unroll 1
    for (int t = 0; t < ntiles; t++) {
        const int cur = t & 1;
        CP_WAIT0();
        __syncthreads();
        if (t == 0) {
#pragma unroll
            for (int kk = 0; kk < 4; kk++) {
                const uint32_t off = swz((uint32_t)(wid * 16 + lrow) * 128u
                                         + (uint32_t)(kk * 16 + lkh * 8) * 2u);
                LDSM_X4(qh[kk][0], qh[kk][1], qh[kk][2], qh[kk][3], sb + off);
                LDSM_X4(ql[kk][0], ql[kk][1], ql[kk][2], ql[kk][3], sb + 16384 + off);
            }
        }
        if (t + 1 < ntiles) load_kv(cur ^ 1, t + 1);

        const uint32_t st = sb + 32768 + (uint32_t)cur * 32768;

        // ---- S = Q K^T (64 cols per warp), K-frag double buffered ----
        float s[8][4];
#pragma unroll
        for (int j = 0; j < 8; j++)
#pragma unroll
            for (int c = 0; c < 4; c++) s[j][c] = 0.f;

        {
            uint32_t kfh[2][4], kfl[2][4];
            auto ldK = [&](int fb, int idx) {
                const int kk = idx >> 2, jj = idx & 3;
                const uint32_t off = swz((uint32_t)(jj * 16 + lrow) * 128u
                                         + (uint32_t)(kk * 16 + lkh * 8) * 2u);
                LDSM_X4(kfh[fb][0], kfh[fb][1], kfh[fb][2], kfh[fb][3], st + off);
                LDSM_X4(kfl[fb][0], kfl[fb][1], kfl[fb][2], kfl[fb][3], st + 8192 + off);
            };
            ldK(0, 0);
#pragma unroll
            for (int idx = 0; idx < 16; idx++) {
                const int fb = idx & 1;
                if (idx < 15) ldK(fb ^ 1, idx + 1);
                const int kk = idx >> 2, jj = idx & 3;
                MMA16816(s[2*jj],   qh[kk], kfh[fb][0], kfh[fb][2]);
                MMA16816(s[2*jj+1], qh[kk], kfh[fb][1], kfh[fb][3]);
                MMA16816(s[2*jj],   qh[kk], kfl[fb][0], kfl[fb][2]);
                MMA16816(s[2*jj+1], qh[kk], kfl[fb][1], kfl[fb][3]);
                MMA16816(s[2*jj],   ql[kk], kfh[fb][0], kfh[fb][2]);
                MMA16816(s[2*jj+1], ql[kk], kfh[fb][1], kfh[fb][3]);
            }
        }

        // ---- causal mask (only the last two 64-wide tiles can cross the diag) ----
        if (t >= ntiles - 2) {
            const int row0 = i0 + rt0;
#pragma unroll
            for (int j = 0; j < 8; j++) {
#pragma unroll
                for (int c = 0; c < 2; c++) {
                    const int ct = t * 64 + j * 8 + (lane & 3) * 2 + c;
                    if (ct > row0)     s[j][c]     = -INFINITY;
                    if (ct > row0 + 8) s[j][c + 2] = -INFINITY;
                }
            }
        }

        // ---- online softmax ----
        float mx0 = -INFINITY, mx1 = -INFINITY;
#pragma unroll
        for (int j = 0; j < 8; j++) {
            mx0 = fmaxf(mx0, fmaxf(s[j][0], s[j][1]));
            mx1 = fmaxf(mx1, fmaxf(s[j][2], s[j][3]));
        }
        mx0 = fmaxf(mx0, __shfl_xor_sync(0xffffffffu, mx0, 1));
        mx0 = fmaxf(mx0, __shfl_xor_sync(0xffffffffu, mx0, 2));
        mx1 = fmaxf(mx1, __shfl_xor_sync(0xffffffffu, mx1, 1));
        mx1 = fmaxf(mx1, __shfl_xor_sync(0xffffffffu, mx1, 2));
        const float mn0 = fmaxf(m0r, mx0);
        const float mn1 = fmaxf(m1r, mx1);
        const float c0 = ex2f((m0r - mn0) * SC);
        const float c1 = ex2f((m1r - mn1) * SC);
        m0r = mn0; m1r = mn1;

        float ls0 = 0.f, ls1 = 0.f;
#pragma unroll
        for (int j = 0; j < 8; j++) {
            s[j][0] = ex2f((s[j][0] - mn0) * SC);
            s[j][1] = ex2f((s[j][1] - mn0) * SC);
            s[j][2] = ex2f((s[j][2] - mn1) * SC);
            s[j][3] = ex2f((s[j][3] - mn1) * SC);
            ls0 += s[j][0] + s[j][1];
            ls1 += s[j][2] + s[j][3];
        }
        ls0 += __shfl_xor_sync(0xffffffffu, ls0, 1);
        ls0 += __shfl_xor_sync(0xffffffffu, ls0, 2);
        ls1 += __shfl_xor_sync(0xffffffffu, ls1, 1);
        ls1 += __shfl_xor_sync(0xffffffffu, ls1, 2);
        l0 = l0 * c0 + ls0;
        l1 = l1 * c1 + ls1;
#pragma unroll
        for (int j = 0; j < 8; j++) {
            o[j][0] *= c0; o[j][1] *= c0; o[j][2] *= c1; o[j][3] *= c1;
        }

        // ---- O += P V, V-frag double buffered ----
        {
            uint32_t vfh[2][4], vfl[2][4];
            auto ldV = [&](int fb, int idx) {
                const int kk = idx >> 2, jj = idx & 3;
                const uint32_t off = swz((uint32_t)(kk * 16 + lrow) * 128u
                                         + (uint32_t)(jj * 16 + lkh * 8) * 2u);
                LDSM_X4_T(vfh[fb][0], vfh[fb][1], vfh[fb][2], vfh[fb][3], st + 16384 + off);
                LDSM_X4_T(vfl[fb][0], vfl[fb][1], vfl[fb][2], vfl[fb][3], st + 24576 + off);
            };
            ldV(0, 0);
            uint32_t ahi[4], alo[4];
#pragma unroll
            for (int idx = 0; idx < 16; idx++) {
                const int fb = idx & 1;
                const int kk = idx >> 2, jj = idx & 3;
                if (jj == 0) {
                    split2(s[2*kk][0],   s[2*kk][1],   ahi[0], alo[0]);
                    split2(s[2*kk][2],   s[2*kk][3],   ahi[1], alo[1]);
                    split2(s[2*kk+1][0], s[2*kk+1][1], ahi[2], alo[2]);
                    split2(s[2*kk+1][2], s[2*kk+1][3], ahi[3], alo[3]);
                }
                if (idx < 15) ldV(fb ^ 1, idx + 1);
                MMA16816(o[2*jj],   ahi, vfh[fb][0], vfh[fb][1]);
                MMA16816(o[2*jj+1], ahi, vfh[fb][2], vfh[fb][3]);
                MMA16816(o[2*jj],   alo, vfh[fb][0], vfh[fb][1]);
                MMA16816(o[2*jj+1], alo, vfh[fb][2], vfh[fb][3]);
                MMA16816(o[2*jj],   ahi, vfl[fb][0], vfl[fb][1]);
                MMA16816(o[2*jj+1], ahi, vfl[fb][2], vfl[fb][3]);
            }
        }
    }

    // ---- epilogue: normalize, write att as bf16 hi/lo at [b*T+t][h*64+d] ----
    const float inv0 = 1.0f / l0;
    const float inv1 = 1.0f / l1;
    const int colb = h * DHEAD + (lane & 3) * 2;
    const size_t row0 = (size_t)(b * TSEQ + i0 + rt0);
#pragma unroll
    for (int j = 0; j < 8; j++) {
        uint32_t hi, lo;
        const size_t idx0 = row0 * EDIM + colb + j * 8;
        split2(o[j][0] * inv0, o[j][1] * inv0, hi, lo);
        *(uint32_t*)(g_athi + idx0) = hi;
        *(uint32_t*)(g_atlo + idx0) = lo;
        const size_t idx1 = idx0 + (size_t)8 * EDIM;
        split2(o[j][2] * inv1, o[j][3] * inv1, hi, lo);
        *(uint32_t*)(g_athi + idx1) = hi;
        *(uint32_t*)(g_atlo + idx1) = lo;
    }
}

// ---------------------------------------------------------------------------
extern "C" void kernel_launch(void* const* d_in, const int* in_sizes, int n_in,
                              void* d_out, int out_size)
{
    const float* x  = (const float*)d_in[0];
    const float* Wq = (const float*)d_in[2];
    const float* Wk = (const float*)d_in[3];
    const float* Wv = (const float*)d_in[4];
    const float* Wo = (const float*)d_in[5];
    float* out = (float*)d_out;

    cudaFuncSetAttribute(mm64, cudaFuncAttributeMaxDynamicSharedMemorySize, 2 * MMSTAGE);
    cudaFuncSetAttribute(flash_mma, cudaFuncAttributeMaxDynamicSharedMemorySize, FA_SMEM);

    // 1) fp32 -> bf16 hi/lo conversions
    conv_elem<<<(MTOT * EDIM) / (256 * 4), 256>>>(x, 0);
    conv_elem<<<(EDIM * EDIM) / (256 * 4), 256>>>(Wo, 1);
    {
        dim3 g(EDIM / 32, NHEAD, 3);
        conv_w_t<<<g, 256>>>(Wq, Wk, Wv);
    }

    // 2) QKV projection -> bf16 hi/lo [z][h][m][d]
    {
        dim3 g(EDIM / 64, MTOT / 128, 3);
        mm64<<<g, 256, 2 * MMSTAGE>>>(nullptr, 0);
    }

    // 3) Flash attention (bf16x3 tensor cores)
    {
        dim3 g(TSEQ / 128, NHEAD * BATCH);
        flash_mma<<<g, 256, FA_SMEM>>>();
    }

    // 4) Output projection
    {
        dim3 g(EDIM / 64, MTOT / 128, 1);
        mm64<<<g, 256, 2 * MMSTAGE>>>(out, 1);
    }
}

// round 17
// speedup vs baseline: 1.0392x; 1.0091x over previous
#include <cuda_runtime.h>
#include <cuda_bf16.h>
#include <math.h>
#include <stdint.h>

#define BATCH 2
#define TSEQ  2048
#define EDIM  1024
#define NHEAD 16
#define DHEAD 64
#define MTOT  (BATCH*TSEQ)   // 4096

// ---------------------------------------------------------------------------
// Scratch (static device globals: allocation-free, graph-safe)
// ---------------------------------------------------------------------------
static __device__ __nv_bfloat16  g_xhi[(size_t)MTOT * EDIM];
static __device__ __nv_bfloat16  g_xlo[(size_t)MTOT * EDIM];
static __device__ __nv_bfloat16  g_wthi[(size_t)3 * EDIM * EDIM];   // [z][n=h*64+d][e]
static __device__ __nv_bfloat16  g_wtlo[(size_t)3 * EDIM * EDIM];
static __device__ __nv_bfloat16  g_wohi[(size_t)EDIM * EDIM];       // [n][k]
static __device__ __nv_bfloat16  g_wolo[(size_t)EDIM * EDIM];
static __device__ __nv_bfloat16  g_athi[(size_t)MTOT * EDIM];       // [m][h*64+d]
static __device__ __nv_bfloat16  g_atlo[(size_t)MTOT * EDIM];
// QKV in bf16 hi/lo: [z][h][m=b*T+t][d]
static __device__ __nv_bfloat16  g_pqkvh[(size_t)3 * NHEAD * MTOT * DHEAD];
static __device__ __nv_bfloat16  g_pqkvl[(size_t)3 * NHEAD * MTOT * DHEAD];

// ---------------------------------------------------------------------------
// Portable (sm_100 base) tensor-core helpers
// ---------------------------------------------------------------------------
__device__ __forceinline__ uint32_t smem_u32(const void* p) {
    uint32_t a;
    asm("{ .reg .u64 t; cvta.to.shared.u64 t, %1; cvt.u32.u64 %0, t; }" : "=r"(a) : "l"(p));
    return a;
}
#define CP_ASYNC16(saddr, gptr) \
    asm volatile("cp.async.cg.shared.global [%0], [%1], 16;" :: "r"(saddr), "l"(gptr))
#define CP_COMMIT() asm volatile("cp.async.commit_group;" ::: "memory")
#define CP_WAIT0()  asm volatile("cp.async.wait_group 0;" ::: "memory")

#define LDSM_X4(r0, r1, r2, r3, addr) \
    asm volatile("ldmatrix.sync.aligned.m8n8.x4.shared.b16 {%0,%1,%2,%3}, [%4];" \
                 : "=r"(r0), "=r"(r1), "=r"(r2), "=r"(r3) : "r"(addr))
#define LDSM_X4_T(r0, r1, r2, r3, addr) \
    asm volatile("ldmatrix.sync.aligned.m8n8.x4.trans.shared.b16 {%0,%1,%2,%3}, [%4];" \
                 : "=r"(r0), "=r"(r1), "=r"(r2), "=r"(r3) : "r"(addr))

#define MMA16816(d, a, b0, b1) \
    asm volatile("mma.sync.aligned.m16n8k16.row.col.f32.bf16.bf16.f32 " \
                 "{%0,%1,%2,%3}, {%4,%5,%6,%7}, {%8,%9}, {%0,%1,%2,%3};" \
                 : "+f"((d)[0]), "+f"((d)[1]), "+f"((d)[2]), "+f"((d)[3]) \
                 : "r"((a)[0]), "r"((a)[1]), "r"((a)[2]), "r"((a)[3]), "r"(b0), "r"(b1))

__device__ __forceinline__ uint32_t swz(uint32_t off) {
    return off ^ ((off >> 3) & 0x70);
}
__device__ __forceinline__ float ex2f(float x) {
    float y; asm("ex2.approx.f32 %0, %1;" : "=f"(y) : "f"(x)); return y;
}
__device__ __forceinline__ void split2(float v0, float v1, uint32_t& hi, uint32_t& lo) {
    __nv_bfloat16 h0 = __float2bfloat16(v0), h1 = __float2bfloat16(v1);
    __nv_bfloat162 hp(h0, h1);
    hi = *(const uint32_t*)&hp;
    __nv_bfloat162 lp(__float2bfloat16(v0 - __bfloat162float(h0)),
                      __float2bfloat16(v1 - __bfloat162float(h1)));
    lo = *(const uint32_t*)&lp;
}

// ---------------------------------------------------------------------------
// Fused conversion kernel: one launch does all fp32 -> bf16 hi/lo prep.
//   blocks [0, 4096)        : x  -> g_xhi/g_xlo          (float4 per thread)
//   blocks [4096, 5120)     : Wo -> g_wohi/g_wolo
//   blocks [5120, 6656)     : Wq/Wk/Wv transpose-convert -> g_wthi/g_wtlo
// ---------------------------------------------------------------------------
#define CONV_XB   (MTOT * EDIM / (256 * 4))     // 4096
#define CONV_WOB  (EDIM * EDIM / (256 * 4))     // 1024
#define CONV_WTB  (3 * NHEAD * (EDIM / 32))     // 1536

__global__ __launch_bounds__(256) void conv_all(
    const float* __restrict__ x,  const float* __restrict__ Wq,
    const float* __restrict__ Wk, const float* __restrict__ Wv,
    const float* __restrict__ Wo)
{
    __shared__ float tile[32][65];
    const int bid = blockIdx.x;
    const int tid = threadIdx.x;

    if (bid < CONV_XB + CONV_WOB) {
        const bool isx = bid < CONV_XB;
        const float* src = isx ? x : Wo;
        __nv_bfloat16* hi = isx ? g_xhi : g_wohi;
        __nv_bfloat16* lo = isx ? g_xlo : g_wolo;
        const int i4 = (isx ? bid : bid - CONV_XB) * 256 + tid;
        float4 v = *(const float4*)(src + (size_t)i4 * 4);
        uint32_t h0, l0, h1, l1;
        split2(v.x, v.y, h0, l0);
        split2(v.z, v.w, h1, l1);
        *(uint32_t*)(hi + (size_t)i4 * 4)     = h0;
        *(uint32_t*)(hi + (size_t)i4 * 4 + 2) = h1;
        *(uint32_t*)(lo + (size_t)i4 * 4)     = l0;
        *(uint32_t*)(lo + (size_t)i4 * 4 + 2) = l1;
    } else {
        const int idx = bid - (CONV_XB + CONV_WOB);       // 0..1535
        const int z = idx / (NHEAD * (EDIM / 32));
        const int rem = idx % (NHEAD * (EDIM / 32));
        const int h = rem >> 5;
        const int e0 = (rem & 31) * 32;
        const float* W = ((z == 0) ? Wq : (z == 1) ? Wk : Wv) + (size_t)h * EDIM * DHEAD;
        {
            const int e = tid >> 3, d0 = (tid & 7) * 8;
#pragma unroll
            for (int i = 0; i < 8; i++)
                tile[e][d0 + i] = W[(size_t)(e0 + e) * DHEAD + d0 + i];
        }
        __syncthreads();
        {
            const int d = tid >> 2, eo = (tid & 3) * 8;
            const size_t base = (size_t)z * EDIM * EDIM
                              + (size_t)(h * DHEAD + d) * EDIM + e0 + eo;
#pragma unroll
            for (int i = 0; i < 8; i++) {
                float v = tile[eo + i][d];
                __nv_bfloat16 hh = __float2bfloat16(v);
                g_wthi[base + i] = hh;
                g_wtlo[base + i] = __float2bfloat16(v - __bfloat162float(hh));
            }
        }
    }
}

// ---------------------------------------------------------------------------
// bf16x3 mma.sync GEMM, 2 CTAs/SM: CTA 128x64, BK=64, 2-stage cp.async,
// 96KB smem, 8 warps (4M x 2N), warp tile 32x32, register-level fragment
// double buffering + boundary barrier hoisted before the last mmab.
// mode 0: A=x, B=Wt[z], C -> g_pqkvh/l.  mode 1: A=att, B=Wo, C -> out fp32.
// ---------------------------------------------------------------------------
#define MMSTAGE 49152   // Ah 16K | Al 16K | Bh 8K | Bl 8K

__global__ __launch_bounds__(256, 2) void mm64(float* __restrict__ Cout, int mode)
{
    extern __shared__ char smem[];
    const uint32_t sb = smem_u32(smem);
    const int tid = threadIdx.x;
    const int wid = tid >> 5, lane = tid & 31;
    const int z = blockIdx.z;
    const int m0 = blockIdx.y * 128;
    const int n0 = blockIdx.x * 64;

    const __nv_bfloat16* Ah = (mode == 0) ? g_xhi : g_athi;
    const __nv_bfloat16* Al = (mode == 0) ? g_xlo : g_atlo;
    const __nv_bfloat16* Bh = (mode == 0) ? (g_wthi + (size_t)z * EDIM * EDIM) : g_wohi;
    const __nv_bfloat16* Bl = (mode == 0) ? (g_wtlo + (size_t)z * EDIM * EDIM) : g_wolo;

    const int ra  = tid >> 1;
    const int cba = (tid & 1) * 32;
    const int rb  = tid >> 2;
    const int cbb = (tid & 3) * 16;
    const size_t ga_row = (size_t)(m0 + ra) * EDIM;
    const size_t gb_row = (size_t)(n0 + rb) * EDIM;

    auto load_stage = [&](int s, int k0) {
        const uint32_t base = sb + (uint32_t)s * MMSTAGE;
#pragma unroll
        for (int q = 0; q < 4; q++) {
            const int c = cba + q * 8;
            const uint32_t sw = swz((uint32_t)ra * 128u + (uint32_t)c * 2u);
            CP_ASYNC16(base + sw,          Ah + ga_row + k0 + c);
            CP_ASYNC16(base + 16384 + sw,  Al + ga_row + k0 + c);
        }
#pragma unroll
        for (int q = 0; q < 2; q++) {
            const int c = cbb + q * 8;
            const uint32_t sw = swz((uint32_t)rb * 128u + (uint32_t)c * 2u);
            CP_ASYNC16(base + 32768 + sw,  Bh + gb_row + k0 + c);
            CP_ASYNC16(base + 40960 + sw,  Bl + gb_row + k0 + c);
        }
        CP_COMMIT();
    };

    const int wm = wid >> 1;
    const int wn = wid & 1;
    const int lrow = lane & 15;
    const int lkh  = lane >> 4;

    uint32_t ah[2][2][4], al[2][2][4], bh[2][2][4], bl[2][2][4];
    float d[2][4][4];
#pragma unroll
    for (int i = 0; i < 2; i++)
#pragma unroll
        for (int j = 0; j < 4; j++)
#pragma unroll
            for (int c = 0; c < 4; c++) d[i][j][c] = 0.f;

    auto ldfr = [&](int fb, uint32_t st, int ks) {
        const uint32_t kcol = (uint32_t)(ks * 16 + lkh * 8) * 2u;
#pragma unroll
        for (int i = 0; i < 2; i++) {
            const uint32_t off = swz((uint32_t)(wm * 32 + i * 16 + lrow) * 128u + kcol);
            LDSM_X4(ah[fb][i][0], ah[fb][i][1], ah[fb][i][2], ah[fb][i][3], st + off);
            LDSM_X4(al[fb][i][0], al[fb][i][1], al[fb][i][2], al[fb][i][3], st + 16384 + off);
        }
#pragma unroll
        for (int j = 0; j < 2; j++) {
            const uint32_t off = swz((uint32_t)(wn * 32 + j * 16 + lrow) * 128u + kcol);
            LDSM_X4(bh[fb][j][0], bh[fb][j][1], bh[fb][j][2], bh[fb][j][3], st + 32768 + off);
            LDSM_X4(bl[fb][j][0], bl[fb][j][1], bl[fb][j][2], bl[fb][j][3], st + 40960 + off);
        }
    };

    auto mmab = [&](int fb) {
#pragma unroll
        for (int i = 0; i < 2; i++)
#pragma unroll
            for (int j = 0; j < 2; j++) {
                MMA16816(d[i][2*j],   ah[fb][i], bh[fb][j][0], bh[fb][j][2]);
                MMA16816(d[i][2*j+1], ah[fb][i], bh[fb][j][1], bh[fb][j][3]);
            }
#pragma unroll
        for (int i = 0; i < 2; i++)
#pragma unroll
            for (int j = 0; j < 2; j++) {
                MMA16816(d[i][2*j],   ah[fb][i], bl[fb][j][0], bl[fb][j][2]);
                MMA16816(d[i][2*j+1], ah[fb][i], bl[fb][j][1], bl[fb][j][3]);
            }
#pragma unroll
        for (int i = 0; i < 2; i++)
#pragma unroll
            for (int j = 0; j < 2; j++) {
                MMA16816(d[i][2*j],   al[fb][i], bh[fb][j][0], bh[fb][j][2]);
                MMA16816(d[i][2*j+1], al[fb][i], bh[fb][j][1], bh[fb][j][3]);
            }
    };

    load_stage(0, 0);
    CP_WAIT0();
    __syncthreads();
    ldfr(0, sb, 0);
    load_stage(1, 64);

#pragma unroll 1
    for (int kb = 0; kb < 16; kb++) {
        const int cur = kb & 1;
        const uint32_t st = sb + (uint32_t)cur * MMSTAGE;
        ldfr(1, st, 1); mmab(0);
        ldfr(0, st, 2); mmab(1);
        ldfr(1, st, 3); mmab(0);
        if (kb < 15) {
            CP_WAIT0();
            __syncthreads();
            ldfr(0, sb + (uint32_t)(cur ^ 1) * MMSTAGE, 0);
            mmab(1);
            if (kb < 14) load_stage(cur, (kb + 2) * 64);
        } else {
            mmab(1);
        }
    }

    const int qrow = lane >> 2, qcol = (lane & 3) * 2;
#pragma unroll
    for (int i = 0; i < 2; i++) {
#pragma unroll
        for (int j = 0; j < 4; j++) {
            const int n = n0 + wn * 32 + j * 8 + qcol;
            const int m1 = m0 + wm * 32 + i * 16 + qrow;
#pragma unroll
            for (int hh = 0; hh < 2; hh++) {
                const int m = m1 + hh * 8;
                const float v0 = d[i][j][hh * 2 + 0];
                const float v1 = d[i][j][hh * 2 + 1];
                if (mode == 0) {
                    const size_t base = (size_t)(n >> 6) * (MTOT * DHEAD)
                                      + (size_t)m * DHEAD + (n & 63);
                    uint32_t hi, lo;
                    split2(v0, v1, hi, lo);
                    *(uint32_t*)(g_pqkvh + (size_t)z * NHEAD * MTOT * DHEAD + base) = hi;
                    *(uint32_t*)(g_pqkvl + (size_t)z * NHEAD * MTOT * DHEAD + base) = lo;
                } else {
                    float* dst = Cout + (size_t)m * EDIM + n;
                    dst[0] = v0; dst[1] = v1;
                }
            }
        }
    }
}

// ---------------------------------------------------------------------------
// Flash attention, 2 CTAs/SM: 128 q-rows/CTA, KV tiles of 64,
// double-buffered cp.async + register-level fragment double buffering in
// both the S (QK^T) and PV loops.  (round-13 structure, proven best)
// ---------------------------------------------------------------------------
#define FA_SMEM (32768 + 2 * 32768)   // Q hi/lo 32K + 2 KV stages of 32K

__global__ __launch_bounds__(256, 2) void flash_mma()
{
    extern __shared__ char fsm[];
    const uint32_t sb = smem_u32(fsm);
    const int tid = threadIdx.x;
    const int wid = tid >> 5, lane = tid & 31;
    const int h = blockIdx.y >> 1;
    const int b = blockIdx.y & 1;
    const int i0 = (int)(gridDim.x - 1 - blockIdx.x) * 128;  // heavy tiles first
    const int ntiles = i0 / 64 + 2;

    const size_t hb = ((size_t)h * MTOT + (size_t)b * TSEQ) * DHEAD;
    const __nv_bfloat16* Qh = g_pqkvh + hb;
    const __nv_bfloat16* Ql = g_pqkvl + hb;
    const __nv_bfloat16* Kh = g_pqkvh + (size_t)NHEAD * MTOT * DHEAD + hb;
    const __nv_bfloat16* Kl = g_pqkvl + (size_t)NHEAD * MTOT * DHEAD + hb;
    const __nv_bfloat16* Vh = g_pqkvh + (size_t)2 * NHEAD * MTOT * DHEAD + hb;
    const __nv_bfloat16* Vl = g_pqkvl + (size_t)2 * NHEAD * MTOT * DHEAD + hb;

    const int rq  = tid >> 1;
    const int cbq = (tid & 1) * 32;
    const int rk  = tid >> 2;
    const int cbk = (tid & 3) * 16;

    // Q (one-time) + KV stage 0, one commit group
#pragma unroll
    for (int q = 0; q < 4; q++) {
        const int c = cbq + q * 8;
        const uint32_t sw = swz((uint32_t)rq * 128u + (uint32_t)c * 2u);
        CP_ASYNC16(sb + sw,          Qh + (size_t)(i0 + rq) * DHEAD + c);
        CP_ASYNC16(sb + 16384 + sw,  Ql + (size_t)(i0 + rq) * DHEAD + c);
    }
    auto load_kv = [&](int s, int t) {
        const uint32_t base = sb + 32768 + (uint32_t)s * 32768;
        const size_t g = (size_t)(t * 64 + rk) * DHEAD;
#pragma unroll
        for (int q = 0; q < 2; q++) {
            const int c = cbk + q * 8;
            const uint32_t sw = swz((uint32_t)rk * 128u + (uint32_t)c * 2u);
            CP_ASYNC16(base + sw,          Kh + g + c);
            CP_ASYNC16(base + 8192 + sw,   Kl + g + c);
            CP_ASYNC16(base + 16384 + sw,  Vh + g + c);
            CP_ASYNC16(base + 24576 + sw,  Vl + g + c);
        }
        CP_COMMIT();
    };
    load_kv(0, 0);

    const float SC = 1.4426950408889634f * 0.02209708691207961f;  // log2(e)/sqrt(T)

    uint32_t qh[4][4], ql[4][4];
    float o[8][4];
#pragma unroll
    for (int j = 0; j < 8; j++)
#pragma unroll
        for (int c = 0; c < 4; c++) o[j][c] = 0.f;
    float m0r = -INFINITY, m1r = -INFINITY, l0 = 0.f, l1 = 0.f;

    const int rt0 = wid * 16 + (lane >> 2);
    const int lrow = lane & 15;
    const int lkh  = lane >> 4;

#pragma unroll 1
    for (int t = 0; t < ntiles; t++) {
        const int cur = t & 1;
        CP_WAIT0();
        __syncthreads();
        if (t == 0) {
#pragma unroll
            for (int kk = 0; kk < 4; kk++) {
                const uint32_t off = swz((uint32_t)(wid * 16 + lrow) * 128u
                                         + (uint32_t)(kk * 16 + lkh * 8) * 2u);
                LDSM_X4(qh[kk][0], qh[kk][1], qh[kk][2], qh[kk][3], sb + off);
                LDSM_X4(ql[kk][0], ql[kk][1], ql[kk][2], ql[kk][3], sb + 16384 + off);
            }
        }
        if (t + 1 < ntiles) load_kv(cur ^ 1, t + 1);

        const uint32_t st = sb + 32768 + (uint32_t)cur * 32768;

        // ---- S = Q K^T (64 cols per warp), K-frag double buffered ----
        float s[8][4];
#pragma unroll
        for (int j = 0; j < 8; j++)
#pragma unroll
            for (int c = 0; c < 4; c++) s[j][c] = 0.f;

        {
            uint32_t kfh[2][4], kfl[2][4];
            auto ldK = [&](int fb, int idx) {
                const int kk = idx >> 2, jj = idx & 3;
                const uint32_t off = swz((uint32_t)(jj * 16 + lrow) * 128u
                                         + (uint32_t)(kk * 16 + lkh * 8) * 2u);
                LDSM_X4(kfh[fb][0], kfh[fb][1], kfh[fb][2], kfh[fb][3], st + off);
                LDSM_X4(kfl[fb][0], kfl[fb][1], kfl[fb][2], kfl[fb][3], st + 8192 + off);
            };
            ldK(0, 0);
#pragma unroll
            for (int idx = 0; idx < 16; idx++) {
                const int fb = idx & 1;
                if (idx < 15) ldK(fb ^ 1, idx + 1);
                const int kk = idx >> 2, jj = idx & 3;
                MMA16816(s[2*jj],   qh[kk], kfh[fb][0], kfh[fb][2]);
                MMA16816(s[2*jj+1], qh[kk], kfh[fb][1], kfh[fb][3]);
                MMA16816(s[2*jj],   qh[kk], kfl[fb][0], kfl[fb][2]);
                MMA16816(s[2*jj+1], qh[kk], kfl[fb][1], kfl[fb][3]);
                MMA16816(s[2*jj],   ql[kk], kfh[fb][0], kfh[fb][2]);
                MMA16816(s[2*jj+1], ql[kk], kfh[fb][1], kfh[fb][3]);
            }
        }

        // ---- causal mask (only the last two 64-wide tiles can cross the diag) ----
        if (t >= ntiles - 2) {
            const int row0 = i0 + rt0;
#pragma unroll
            for (int j = 0; j < 8; j++) {
#pragma unroll
                for (int c = 0; c < 2; c++) {
                    const int ct = t * 64 + j * 8 + (lane & 3) * 2 + c;
                    if (ct > row0)     s[j][c]     = -INFINITY;
                    if (ct > row0 + 8) s[j][c + 2] = -INFINITY;
                }
            }
        }

        // ---- online softmax ----
        float mx0 = -INFINITY, mx1 = -INFINITY;
#pragma unroll
        for (int j = 0; j < 8; j++) {
            mx0 = fmaxf(mx0, fmaxf(s[j][0], s[j][1]));
            mx1 = fmaxf(mx1, fmaxf(s[j][2], s[j][3]));
        }
        mx0 = fmaxf(mx0, __shfl_xor_sync(0xffffffffu, mx0, 1));
        mx0 = fmaxf(mx0, __shfl_xor_sync(0xffffffffu, mx0, 2));
        mx1 = fmaxf(mx1, __shfl_xor_sync(0xffffffffu, mx1, 1));
        mx1 = fmaxf(mx1, __shfl_xor_sync(0xffffffffu, mx1, 2));
        const float mn0 = fmaxf(m0r, mx0);
        const float mn1 = fmaxf(m1r, mx1);
        const float c0 = ex2f((m0r - mn0) * SC);
        const float c1 = ex2f((m1r - mn1) * SC);
        m0r = mn0; m1r = mn1;

        float ls0 = 0.f, ls1 = 0.f;
#pragma unroll
        for (int j = 0; j < 8; j++) {
            s[j][0] = ex2f((s[j][0] - mn0) * SC);
            s[j][1] = ex2f((s[j][1] - mn0) * SC);
            s[j][2] = ex2f((s[j][2] - mn1) * SC);
            s[j][3] = ex2f((s[j][3] - mn1) * SC);
            ls0 += s[j][0] + s[j][1];
            ls1 += s[j][2] + s[j][3];
        }
        ls0 += __shfl_xor_sync(0xffffffffu, ls0, 1);
        ls0 += __shfl_xor_sync(0xffffffffu, ls0, 2);
        ls1 += __shfl_xor_sync(0xffffffffu, ls1, 1);
        ls1 += __shfl_xor_sync(0xffffffffu, ls1, 2);
        l0 = l0 * c0 + ls0;
        l1 = l1 * c1 + ls1;
#pragma unroll
        for (int j = 0; j < 8; j++) {
            o[j][0] *= c0; o[j][1] *= c0; o[j][2] *= c1; o[j][3] *= c1;
        }

        // ---- O += P V, V-frag double buffered ----
        {
            uint32_t vfh[2][4], vfl[2][4];
            auto ldV = [&](int fb, int idx) {
                const int kk = idx >> 2, jj = idx & 3;
                const uint32_t off = swz((uint32_t)(kk * 16 + lrow) * 128u
                                         + (uint32_t)(jj * 16 + lkh * 8) * 2u);
                LDSM_X4_T(vfh[fb][0], vfh[fb][1], vfh[fb][2], vfh[fb][3], st + 16384 + off);
                LDSM_X4_T(vfl[fb][0], vfl[fb][1], vfl[fb][2], vfl[fb][3], st + 24576 + off);
            };
            ldV(0, 0);
            uint32_t ahi[4], alo[4];
#pragma unroll
            for (int idx = 0; idx < 16; idx++) {
                const int fb = idx & 1;
                const int kk = idx >> 2, jj = idx & 3;
                if (jj == 0) {
                    split2(s[2*kk][0],   s[2*kk][1],   ahi[0], alo[0]);
                    split2(s[2*kk][2],   s[2*kk][3],   ahi[1], alo[1]);
                    split2(s[2*kk+1][0], s[2*kk+1][1], ahi[2], alo[2]);
                    split2(s[2*kk+1][2], s[2*kk+1][3], ahi[3], alo[3]);
                }
                if (idx < 15) ldV(fb ^ 1, idx + 1);
                MMA16816(o[2*jj],   ahi, vfh[fb][0], vfh[fb][1]);
                MMA16816(o[2*jj+1], ahi, vfh[fb][2], vfh[fb][3]);
                MMA16816(o[2*jj],   alo, vfh[fb][0], vfh[fb][1]);
                MMA16816(o[2*jj+1], alo, vfh[fb][2], vfh[fb][3]);
                MMA16816(o[2*jj],   ahi, vfl[fb][0], vfl[fb][1]);
                MMA16816(o[2*jj+1], ahi, vfl[fb][2], vfl[fb][3]);
            }
        }
    }

    // ---- epilogue: normalize, write att as bf16 hi/lo at [b*T+t][h*64+d] ----
    const float inv0 = 1.0f / l0;
    const float inv1 = 1.0f / l1;
    const int colb = h * DHEAD + (lane & 3) * 2;
    const size_t row0 = (size_t)(b * TSEQ + i0 + rt0);
#pragma unroll
    for (int j = 0; j < 8; j++) {
        uint32_t hi, lo;
        const size_t idx0 = row0 * EDIM + colb + j * 8;
        split2(o[j][0] * inv0, o[j][1] * inv0, hi, lo);
        *(uint32_t*)(g_athi + idx0) = hi;
        *(uint32_t*)(g_atlo + idx0) = lo;
        const size_t idx1 = idx0 + (size_t)8 * EDIM;
        split2(o[j][2] * inv1, o[j][3] * inv1, hi, lo);
        *(uint32_t*)(g_athi + idx1) = hi;
        *(uint32_t*)(g_atlo + idx1) = lo;
    }
}

// ---------------------------------------------------------------------------
extern "C" void kernel_launch(void* const* d_in, const int* in_sizes, int n_in,
                              void* d_out, int out_size)
{
    const float* x  = (const float*)d_in[0];
    const float* Wq = (const float*)d_in[2];
    const float* Wk = (const float*)d_in[3];
    const float* Wv = (const float*)d_in[4];
    const float* Wo = (const float*)d_in[5];
    float* out = (float*)d_out;

    cudaFuncSetAttribute(mm64, cudaFuncAttributeMaxDynamicSharedMemorySize, 2 * MMSTAGE);
    cudaFuncSetAttribute(flash_mma, cudaFuncAttributeMaxDynamicSharedMemorySize, FA_SMEM);

    // 1) all fp32 -> bf16 hi/lo conversions, one launch
    conv_all<<<CONV_XB + CONV_WOB + CONV_WTB, 256>>>(x, Wq, Wk, Wv, Wo);

    // 2) QKV projection -> bf16 hi/lo [z][h][m][d]
    {
        dim3 g(EDIM / 64, MTOT / 128, 3);
        mm64<<<g, 256, 2 * MMSTAGE>>>(nullptr, 0);
    }

    // 3) Flash attention (bf16x3 tensor cores)
    {
        dim3 g(TSEQ / 128, NHEAD * BATCH);
        flash_mma<<<g, 256, FA_SMEM>>>();
    }

    // 4) Output projection
    {
        dim3 g(EDIM / 64, MTOT / 128, 1);
        mm64<<<g, 256, 2 * MMSTAGE>>>(out, 1);
    }
}